// round 10
// baseline (speedup 1.0000x reference)
#include <cuda_runtime.h>
#include <cuda_bf16.h>
#include <cstdint>

#define N_NODES 50000
#define N_EDGES 800000
#define D_IN 128
#define N_HEADS 8
#define PER_HEAD 16
#define LEAKY_ALPHA 0.2f

// ---------------- static device scratch (no allocations allowed) ------------
__device__ float g_q[(size_t)N_NODES * 128];         // 25.6 MB
__device__ float g_k[(size_t)N_NODES * 128];         // 25.6 MB
__device__ int   g_count[N_NODES];                   // in-degree histogram
__device__ int   g_offset[N_NODES + 1];              // CSR row offsets
__device__ int   g_cursor[N_NODES];                  // scatter cursors
__device__ int   g_src_sorted[N_EDGES];              // src node per CSR slot

__device__ __forceinline__ float lrelu(float v) {
    return v > 0.0f ? v : LEAKY_ALPHA * v;
}

// ---------------- side stream + events (host objects; created pre-main) ------
static cudaStream_t g_s2;
static cudaEvent_t g_ev_fork, g_ev_join;
static struct StreamInit {
    StreamInit() {
        cudaStreamCreateWithFlags(&g_s2, cudaStreamNonBlocking);
        cudaEventCreateWithFlags(&g_ev_fork, cudaEventDisableTiming);
        cudaEventCreateWithFlags(&g_ev_join, cudaEventDisableTiming);
    }
} g_stream_init;

// ---------------- Kernel 1: Q/K GEMM (R9 config: broadcast-w, persistent) ----
#define GEMM_BLOCK 256
#define GEMM_TILE_N 64
#define COLS_PER_CHUNK 64
#define XS_STRIDE 132
#define GEMM_GRID_X 111

__global__ void __launch_bounds__(GEMM_BLOCK, 3)
qk_gemm_kernel(const float* __restrict__ x,
               const float* __restrict__ wq, const float* __restrict__ bq,
               const float* __restrict__ wk, const float* __restrict__ bk) {
    extern __shared__ float smem[];
    float* ws = smem;                        // [128][64] = 8192 floats (32KB)
    float* xs = smem + 8192;                 // [64][132] = 8448 floats (33KB)
    float* bs = smem + 8192 + 8448;          // 64 floats

    const int t = threadIdx.x;
    const int col0 = blockIdx.y * COLS_PER_CHUNK;  // 0,64,128,192
    const bool is_q = (col0 < 128);
    const float* wsrc = is_q ? wq : wk;
    const float* bsrc = is_q ? bq : bk;
    const int wcol0 = is_q ? col0 : (col0 - 128);

    for (int i = t; i < 128 * COLS_PER_CHUNK; i += GEMM_BLOCK) {
        int d = i >> 6, c = i & 63;
        ws[i] = wsrc[d * 128 + wcol0 + c];
    }
    if (t < COLS_PER_CHUNK) bs[t] = bsrc[wcol0 + t];

    const int warp = t >> 5;
    const int lane = t & 31;
    const int c0 = warp * 8;
    float* gout = is_q ? g_q : g_k;

    for (int n0 = blockIdx.x * GEMM_TILE_N; n0 < N_NODES;
         n0 += gridDim.x * GEMM_TILE_N) {
        __syncthreads();
        for (int i = t; i < GEMM_TILE_N * 32; i += GEMM_BLOCK) {
            int n = i >> 5, c4 = i & 31;
            int gn = n0 + n;
            float4 v = make_float4(0.f, 0.f, 0.f, 0.f);
            if (gn < N_NODES) v = *(const float4*)(x + (size_t)gn * 128 + c4 * 4);
            *(float4*)(xs + n * XS_STRIDE + c4 * 4) = v;
        }
        __syncthreads();

        float acc0[8], acc1[8];
#pragma unroll
        for (int c = 0; c < 8; c++) { acc0[c] = 0.f; acc1[c] = 0.f; }

        const float* xr0 = xs + lane * XS_STRIDE;
        const float* xr1 = xs + (lane + 32) * XS_STRIDE;

#pragma unroll 2
        for (int d = 0; d < 128; d += 4) {
            const float4 xv0 = *(const float4*)(xr0 + d);
            const float4 xv1 = *(const float4*)(xr1 + d);
#pragma unroll
            for (int dd = 0; dd < 4; dd++) {
                const float4 wa = *(const float4*)(ws + (d + dd) * COLS_PER_CHUNK + c0);
                const float4 wb = *(const float4*)(ws + (d + dd) * COLS_PER_CHUNK + c0 + 4);
                const float x0 = ((const float*)&xv0)[dd];
                const float x1 = ((const float*)&xv1)[dd];
                acc0[0] += x0 * wa.x; acc0[1] += x0 * wa.y;
                acc0[2] += x0 * wa.z; acc0[3] += x0 * wa.w;
                acc0[4] += x0 * wb.x; acc0[5] += x0 * wb.y;
                acc0[6] += x0 * wb.z; acc0[7] += x0 * wb.w;
                acc1[0] += x1 * wa.x; acc1[1] += x1 * wa.y;
                acc1[2] += x1 * wa.z; acc1[3] += x1 * wa.w;
                acc1[4] += x1 * wb.x; acc1[5] += x1 * wb.y;
                acc1[6] += x1 * wb.z; acc1[7] += x1 * wb.w;
            }
        }

        const int nodeA = n0 + lane;
        const int nodeB = n0 + 32 + lane;
        if (nodeA < N_NODES) {
            float4 o0, o1;
            o0.x = acc0[0] + bs[c0 + 0]; o0.y = acc0[1] + bs[c0 + 1];
            o0.z = acc0[2] + bs[c0 + 2]; o0.w = acc0[3] + bs[c0 + 3];
            o1.x = acc0[4] + bs[c0 + 4]; o1.y = acc0[5] + bs[c0 + 5];
            o1.z = acc0[6] + bs[c0 + 6]; o1.w = acc0[7] + bs[c0 + 7];
            *(float4*)(gout + (size_t)nodeA * 128 + wcol0 + c0) = o0;
            *(float4*)(gout + (size_t)nodeA * 128 + wcol0 + c0 + 4) = o1;
        }
        if (nodeB < N_NODES) {
            float4 o0, o1;
            o0.x = acc1[0] + bs[c0 + 0]; o0.y = acc1[1] + bs[c0 + 1];
            o0.z = acc1[2] + bs[c0 + 2]; o0.w = acc1[3] + bs[c0 + 3];
            o1.x = acc1[4] + bs[c0 + 4]; o1.y = acc1[5] + bs[c0 + 5];
            o1.z = acc1[6] + bs[c0 + 6]; o1.w = acc1[7] + bs[c0 + 7];
            *(float4*)(gout + (size_t)nodeB * 128 + wcol0 + c0) = o0;
            *(float4*)(gout + (size_t)nodeB * 128 + wcol0 + c0 + 4) = o1;
        }
    }
}

// ---------------- CSR build: histogram -> scan -> scatter --------------------
__global__ void hist_kernel(const int* __restrict__ etgt) {
    int i = blockIdx.x * blockDim.x + threadIdx.x;
    if (i < N_EDGES) atomicAdd(&g_count[etgt[i]], 1);
}

#define SCAN_THREADS 1024
__global__ void scan_kernel() {
    __shared__ int partial[SCAN_THREADS];
    const int t = threadIdx.x;
    const int CHUNK = (N_NODES + SCAN_THREADS - 1) / SCAN_THREADS;  // 49
    const int base = t * CHUNK;

    int s = 0;
    for (int i = 0; i < CHUNK; i++) {
        int idx = base + i;
        if (idx < N_NODES) s += g_count[idx];
    }
    partial[t] = s;
    __syncthreads();

    for (int off = 1; off < SCAN_THREADS; off <<= 1) {
        int u = (t >= off) ? partial[t - off] : 0;
        __syncthreads();
        partial[t] += u;
        __syncthreads();
    }

    int run = partial[t] - s;
    for (int i = 0; i < CHUNK; i++) {
        int idx = base + i;
        if (idx < N_NODES) {
            g_offset[idx] = run;
            g_cursor[idx] = run;
            run += g_count[idx];
        }
    }
    if (t == SCAN_THREADS - 1) g_offset[N_NODES] = partial[SCAN_THREADS - 1];
}

__global__ void scatter_kernel(const int* __restrict__ esrc,
                               const int* __restrict__ etgt) {
    int i = blockIdx.x * blockDim.x + threadIdx.x;
    if (i < N_EDGES) {
        int pos = atomicAdd(&g_cursor[etgt[i]], 1);
        g_src_sorted[pos] = esrc[i];
    }
}

// ---------------- Kernel 2: per-node gather, cross-group pipelined -----------
// Double-buffered groups of 4 edges: group g+1's shuffles and k-row loads are
// issued BEFORE group g's math, hiding the ~250-cyc L2 latency that was fully
// exposed per group in the serial version.
__global__ void __launch_bounds__(256)
gather_kernel(const float* __restrict__ attn, float* __restrict__ out) {
    __shared__ float a_s[128];
    if (threadIdx.x < 128) a_s[threadIdx.x] = attn[threadIdx.x];
    __syncthreads();

    const int node = (blockIdx.x * blockDim.x + threadIdx.x) >> 5;
    if (node >= N_NODES) return;
    const int lane = threadIdx.x & 31;
    const int part = lane & 3;
    const int h = lane >> 2;

    const float a0 = a_s[(part * 4 + 0) * 8 + h];
    const float a1 = a_s[(part * 4 + 1) * 8 + h];
    const float a2 = a_s[(part * 4 + 2) * 8 + h];
    const float a3 = a_s[(part * 4 + 3) * 8 + h];

    const float4 qv = *(const float4*)(g_q + (size_t)node * 128 + lane * 4);

    const int start = g_offset[node];
    const int end = g_offset[node + 1];

    float4 acc = make_float4(0.f, 0.f, 0.f, 0.f);
    float dsum = 0.f;

    for (int b = start; b < end; b += 32) {
        const int cnt = min(32, end - b);
        const int src_l = (lane < cnt) ? g_src_sorted[b + lane] : 0;

        int j = 0;
        if (cnt >= 4) {
            // prologue: load group 0
            int s0 = __shfl_sync(0xffffffffu, src_l, 0);
            int s1 = __shfl_sync(0xffffffffu, src_l, 1);
            int s2 = __shfl_sync(0xffffffffu, src_l, 2);
            int s3 = __shfl_sync(0xffffffffu, src_l, 3);
            float4 k0 = *(const float4*)(g_k + (size_t)s0 * 128 + lane * 4);
            float4 k1 = *(const float4*)(g_k + (size_t)s1 * 128 + lane * 4);
            float4 k2 = *(const float4*)(g_k + (size_t)s2 * 128 + lane * 4);
            float4 k3 = *(const float4*)(g_k + (size_t)s3 * 128 + lane * 4);

            while (true) {
                const int jn = j + 4;
                const bool more = (jn + 4 <= cnt);   // warp-uniform
                float4 n0, n1, n2, n3;
                if (more) {
                    // issue next group's loads BEFORE current group's math
                    int t0 = __shfl_sync(0xffffffffu, src_l, jn);
                    int t1 = __shfl_sync(0xffffffffu, src_l, jn + 1);
                    int t2 = __shfl_sync(0xffffffffu, src_l, jn + 2);
                    int t3 = __shfl_sync(0xffffffffu, src_l, jn + 3);
                    n0 = *(const float4*)(g_k + (size_t)t0 * 128 + lane * 4);
                    n1 = *(const float4*)(g_k + (size_t)t1 * 128 + lane * 4);
                    n2 = *(const float4*)(g_k + (size_t)t2 * 128 + lane * 4);
                    n3 = *(const float4*)(g_k + (size_t)t3 * 128 + lane * 4);
                }

                float p0 = lrelu(qv.x + k0.x) * a0 + lrelu(qv.y + k0.y) * a1 +
                           lrelu(qv.z + k0.z) * a2 + lrelu(qv.w + k0.w) * a3;
                float p1 = lrelu(qv.x + k1.x) * a0 + lrelu(qv.y + k1.y) * a1 +
                           lrelu(qv.z + k1.z) * a2 + lrelu(qv.w + k1.w) * a3;
                float p2 = lrelu(qv.x + k2.x) * a0 + lrelu(qv.y + k2.y) * a1 +
                           lrelu(qv.z + k2.z) * a2 + lrelu(qv.w + k2.w) * a3;
                float p3 = lrelu(qv.x + k3.x) * a0 + lrelu(qv.y + k3.y) * a1 +
                           lrelu(qv.z + k3.z) * a2 + lrelu(qv.w + k3.w) * a3;

                p0 += __shfl_xor_sync(0xffffffffu, p0, 1);
                p1 += __shfl_xor_sync(0xffffffffu, p1, 1);
                p2 += __shfl_xor_sync(0xffffffffu, p2, 1);
                p3 += __shfl_xor_sync(0xffffffffu, p3, 1);
                p0 += __shfl_xor_sync(0xffffffffu, p0, 2);
                p1 += __shfl_xor_sync(0xffffffffu, p1, 2);
                p2 += __shfl_xor_sync(0xffffffffu, p2, 2);
                p3 += __shfl_xor_sync(0xffffffffu, p3, 2);

                const float u0 = __expf(p0);
                const float u1 = __expf(p1);
                const float u2 = __expf(p2);
                const float u3 = __expf(p3);

                acc.x += u0 * k0.x + u1 * k1.x + u2 * k2.x + u3 * k3.x;
                acc.y += u0 * k0.y + u1 * k1.y + u2 * k2.y + u3 * k3.y;
                acc.z += u0 * k0.z + u1 * k1.z + u2 * k2.z + u3 * k3.z;
                acc.w += u0 * k0.w + u1 * k1.w + u2 * k2.w + u3 * k3.w;
                dsum += (u0 + u1) + (u2 + u3);

                j = jn;
                if (!more) break;
                k0 = n0; k1 = n1; k2 = n2; k3 = n3;
            }
        }
        // tail (0..3 edges)
        for (; j < cnt; j++) {
            const int s0 = __shfl_sync(0xffffffffu, src_l, j);
            const float4 k0 = *(const float4*)(g_k + (size_t)s0 * 128 + lane * 4);
            float p0 = lrelu(qv.x + k0.x) * a0 + lrelu(qv.y + k0.y) * a1 +
                       lrelu(qv.z + k0.z) * a2 + lrelu(qv.w + k0.w) * a3;
            p0 += __shfl_xor_sync(0xffffffffu, p0, 1);
            p0 += __shfl_xor_sync(0xffffffffu, p0, 2);
            const float u0 = __expf(p0);
            acc.x += u0 * k0.x;
            acc.y += u0 * k0.y;
            acc.z += u0 * k0.z;
            acc.w += u0 * k0.w;
            dsum += u0;
        }
    }

    const float inv = (dsum > 0.f) ? 1.f / dsum : 0.f;
    float4 o;
    o.x = fmaxf(acc.x * inv, 0.f);
    o.y = fmaxf(acc.y * inv, 0.f);
    o.z = fmaxf(acc.z * inv, 0.f);
    o.w = fmaxf(acc.w * inv, 0.f);
    *(float4*)(out + (size_t)node * 128 + lane * 4) = o;
}

// ---------------- launch ------------------------------------------------------
extern "C" void kernel_launch(void* const* d_in, const int* in_sizes, int n_in,
                              void* d_out, int out_size) {
    const float* x    = (const float*)d_in[0];
    const float* wq   = (const float*)d_in[1];
    const float* bq   = (const float*)d_in[2];
    const float* wk   = (const float*)d_in[3];
    const float* bk   = (const float*)d_in[4];
    const float* attn = (const float*)d_in[5];
    const int*   esrc = (const int*)d_in[6];
    const int*   etgt = (const int*)d_in[7];
    float* out = (float*)d_out;

    void* count_ptr = nullptr;
    cudaGetSymbolAddress(&count_ptr, g_count);

    // ---- fork: CSR build on side stream, GEMM on main stream (overlapped) ----
    cudaEventRecord(g_ev_fork, 0);
    cudaStreamWaitEvent(g_s2, g_ev_fork, 0);

    cudaMemsetAsync(count_ptr, 0, N_NODES * sizeof(int), g_s2);
    hist_kernel<<<(N_EDGES + 255) / 256, 256, 0, g_s2>>>(etgt);
    scan_kernel<<<1, SCAN_THREADS, 0, g_s2>>>();
    scatter_kernel<<<(N_EDGES + 255) / 256, 256, 0, g_s2>>>(esrc, etgt);
    cudaEventRecord(g_ev_join, g_s2);

    // main stream: persistent broadcast-w Q/K GEMM (~65.3KB smem, 3 CTAs/SM)
    static const size_t gemm_smem = (8192 + 8448 + 64) * sizeof(float);
    cudaFuncSetAttribute(qk_gemm_kernel, cudaFuncAttributeMaxDynamicSharedMemorySize,
                         (int)gemm_smem);
    dim3 gemm_grid(GEMM_GRID_X, 4);
    qk_gemm_kernel<<<gemm_grid, GEMM_BLOCK, gemm_smem>>>(x, wq, bq, wk, bk);

    // ---- join: gather needs both GEMM (program order) and CSR (event) -------
    cudaStreamWaitEvent(0, g_ev_join, 0);
    gather_kernel<<<(N_NODES * 32 + 255) / 256, 256>>>(attn, out);
}

// round 11
// speedup vs baseline: 1.0369x; 1.0369x over previous
#include <cuda_runtime.h>
#include <cuda_bf16.h>
#include <cstdint>

#define N_NODES 50000
#define N_EDGES 800000
#define D_IN 128
#define N_HEADS 8
#define PER_HEAD 16
#define LEAKY_ALPHA 0.2f

// ---------------- static device scratch (no allocations allowed) ------------
__device__ float g_q[(size_t)N_NODES * 128];         // 25.6 MB
__device__ float g_k[(size_t)N_NODES * 128];         // 25.6 MB
__device__ int   g_count[N_NODES];                   // in-degree histogram
__device__ int   g_offset[N_NODES + 1];              // CSR row offsets
__device__ int   g_cursor[N_NODES];                  // scatter cursors
__device__ int   g_src_sorted[N_EDGES];              // src node per CSR slot

__device__ __forceinline__ float lrelu(float v) {
    return v > 0.0f ? v : LEAKY_ALPHA * v;
}

// ---------------- side stream + events (host objects; created pre-main) ------
static cudaStream_t g_s2;
static cudaEvent_t g_ev_fork, g_ev_join;
static struct StreamInit {
    StreamInit() {
        cudaStreamCreateWithFlags(&g_s2, cudaStreamNonBlocking);
        cudaEventCreateWithFlags(&g_ev_fork, cudaEventDisableTiming);
        cudaEventCreateWithFlags(&g_ev_join, cudaEventDisableTiming);
    }
} g_stream_init;

// ---------------- Kernel 1: Q/K GEMM (R9 config: broadcast-w, persistent) ----
#define GEMM_BLOCK 256
#define GEMM_TILE_N 64
#define COLS_PER_CHUNK 64
#define XS_STRIDE 132
#define GEMM_GRID_X 111

__global__ void __launch_bounds__(GEMM_BLOCK, 3)
qk_gemm_kernel(const float* __restrict__ x,
               const float* __restrict__ wq, const float* __restrict__ bq,
               const float* __restrict__ wk, const float* __restrict__ bk) {
    extern __shared__ float smem[];
    float* ws = smem;                        // [128][64] = 8192 floats (32KB)
    float* xs = smem + 8192;                 // [64][132] = 8448 floats (33KB)
    float* bs = smem + 8192 + 8448;          // 64 floats

    const int t = threadIdx.x;
    const int col0 = blockIdx.y * COLS_PER_CHUNK;  // 0,64,128,192
    const bool is_q = (col0 < 128);
    const float* wsrc = is_q ? wq : wk;
    const float* bsrc = is_q ? bq : bk;
    const int wcol0 = is_q ? col0 : (col0 - 128);

    for (int i = t; i < 128 * COLS_PER_CHUNK; i += GEMM_BLOCK) {
        int d = i >> 6, c = i & 63;
        ws[i] = wsrc[d * 128 + wcol0 + c];
    }
    if (t < COLS_PER_CHUNK) bs[t] = bsrc[wcol0 + t];

    const int warp = t >> 5;
    const int lane = t & 31;
    const int c0 = warp * 8;
    float* gout = is_q ? g_q : g_k;

    for (int n0 = blockIdx.x * GEMM_TILE_N; n0 < N_NODES;
         n0 += gridDim.x * GEMM_TILE_N) {
        __syncthreads();
        for (int i = t; i < GEMM_TILE_N * 32; i += GEMM_BLOCK) {
            int n = i >> 5, c4 = i & 31;
            int gn = n0 + n;
            float4 v = make_float4(0.f, 0.f, 0.f, 0.f);
            if (gn < N_NODES) v = *(const float4*)(x + (size_t)gn * 128 + c4 * 4);
            *(float4*)(xs + n * XS_STRIDE + c4 * 4) = v;
        }
        __syncthreads();

        float acc0[8], acc1[8];
#pragma unroll
        for (int c = 0; c < 8; c++) { acc0[c] = 0.f; acc1[c] = 0.f; }

        const float* xr0 = xs + lane * XS_STRIDE;
        const float* xr1 = xs + (lane + 32) * XS_STRIDE;

#pragma unroll 2
        for (int d = 0; d < 128; d += 4) {
            const float4 xv0 = *(const float4*)(xr0 + d);
            const float4 xv1 = *(const float4*)(xr1 + d);
#pragma unroll
            for (int dd = 0; dd < 4; dd++) {
                const float4 wa = *(const float4*)(ws + (d + dd) * COLS_PER_CHUNK + c0);
                const float4 wb = *(const float4*)(ws + (d + dd) * COLS_PER_CHUNK + c0 + 4);
                const float x0 = ((const float*)&xv0)[dd];
                const float x1 = ((const float*)&xv1)[dd];
                acc0[0] += x0 * wa.x; acc0[1] += x0 * wa.y;
                acc0[2] += x0 * wa.z; acc0[3] += x0 * wa.w;
                acc0[4] += x0 * wb.x; acc0[5] += x0 * wb.y;
                acc0[6] += x0 * wb.z; acc0[7] += x0 * wb.w;
                acc1[0] += x1 * wa.x; acc1[1] += x1 * wa.y;
                acc1[2] += x1 * wa.z; acc1[3] += x1 * wa.w;
                acc1[4] += x1 * wb.x; acc1[5] += x1 * wb.y;
                acc1[6] += x1 * wb.z; acc1[7] += x1 * wb.w;
            }
        }

        const int nodeA = n0 + lane;
        const int nodeB = n0 + 32 + lane;
        if (nodeA < N_NODES) {
            float4 o0, o1;
            o0.x = acc0[0] + bs[c0 + 0]; o0.y = acc0[1] + bs[c0 + 1];
            o0.z = acc0[2] + bs[c0 + 2]; o0.w = acc0[3] + bs[c0 + 3];
            o1.x = acc0[4] + bs[c0 + 4]; o1.y = acc0[5] + bs[c0 + 5];
            o1.z = acc0[6] + bs[c0 + 6]; o1.w = acc0[7] + bs[c0 + 7];
            *(float4*)(gout + (size_t)nodeA * 128 + wcol0 + c0) = o0;
            *(float4*)(gout + (size_t)nodeA * 128 + wcol0 + c0 + 4) = o1;
        }
        if (nodeB < N_NODES) {
            float4 o0, o1;
            o0.x = acc1[0] + bs[c0 + 0]; o0.y = acc1[1] + bs[c0 + 1];
            o0.z = acc1[2] + bs[c0 + 2]; o0.w = acc1[3] + bs[c0 + 3];
            o1.x = acc1[4] + bs[c0 + 4]; o1.y = acc1[5] + bs[c0 + 5];
            o1.z = acc1[6] + bs[c0 + 6]; o1.w = acc1[7] + bs[c0 + 7];
            *(float4*)(gout + (size_t)nodeB * 128 + wcol0 + c0) = o0;
            *(float4*)(gout + (size_t)nodeB * 128 + wcol0 + c0 + 4) = o1;
        }
    }
}

// ---------------- CSR build: histogram -> scan -> scatter --------------------
__global__ void hist_kernel(const int* __restrict__ etgt) {
    int i = blockIdx.x * blockDim.x + threadIdx.x;
    if (i < N_EDGES) atomicAdd(&g_count[etgt[i]], 1);
}

#define SCAN_THREADS 1024
__global__ void scan_kernel() {
    __shared__ int partial[SCAN_THREADS];
    const int t = threadIdx.x;
    const int CHUNK = (N_NODES + SCAN_THREADS - 1) / SCAN_THREADS;  // 49
    const int base = t * CHUNK;

    int s = 0;
    for (int i = 0; i < CHUNK; i++) {
        int idx = base + i;
        if (idx < N_NODES) s += g_count[idx];
    }
    partial[t] = s;
    __syncthreads();

    for (int off = 1; off < SCAN_THREADS; off <<= 1) {
        int u = (t >= off) ? partial[t - off] : 0;
        __syncthreads();
        partial[t] += u;
        __syncthreads();
    }

    int run = partial[t] - s;
    for (int i = 0; i < CHUNK; i++) {
        int idx = base + i;
        if (idx < N_NODES) {
            g_offset[idx] = run;
            g_cursor[idx] = run;
            run += g_count[idx];
        }
    }
    if (t == SCAN_THREADS - 1) g_offset[N_NODES] = partial[SCAN_THREADS - 1];
}

__global__ void scatter_kernel(const int* __restrict__ esrc,
                               const int* __restrict__ etgt) {
    int i = blockIdx.x * blockDim.x + threadIdx.x;
    if (i < N_EDGES) {
        int pos = atomicAdd(&g_cursor[etgt[i]], 1);
        g_src_sorted[pos] = esrc[i];
    }
}

// ---------------- Kernel 2: per-node gather (exact R9 known-good, MLP=4) -----
__global__ void __launch_bounds__(256)
gather_kernel(const float* __restrict__ attn, float* __restrict__ out) {
    __shared__ float a_s[128];
    if (threadIdx.x < 128) a_s[threadIdx.x] = attn[threadIdx.x];
    __syncthreads();

    const int node = (blockIdx.x * blockDim.x + threadIdx.x) >> 5;
    if (node >= N_NODES) return;
    const int lane = threadIdx.x & 31;
    const int part = lane & 3;
    const int h = lane >> 2;

    const float a0 = a_s[(part * 4 + 0) * 8 + h];
    const float a1 = a_s[(part * 4 + 1) * 8 + h];
    const float a2 = a_s[(part * 4 + 2) * 8 + h];
    const float a3 = a_s[(part * 4 + 3) * 8 + h];

    const float4 qv = *(const float4*)(g_q + (size_t)node * 128 + lane * 4);

    const int start = g_offset[node];
    const int end = g_offset[node + 1];

    float4 acc = make_float4(0.f, 0.f, 0.f, 0.f);
    float dsum = 0.f;

    for (int b = start; b < end; b += 32) {
        const int cnt = min(32, end - b);
        const int src_l = (lane < cnt) ? g_src_sorted[b + lane] : 0;

        int j = 0;
        for (; j + 4 <= cnt; j += 4) {
            const int s0 = __shfl_sync(0xffffffffu, src_l, j);
            const int s1 = __shfl_sync(0xffffffffu, src_l, j + 1);
            const int s2 = __shfl_sync(0xffffffffu, src_l, j + 2);
            const int s3 = __shfl_sync(0xffffffffu, src_l, j + 3);
            const float4 k0 = *(const float4*)(g_k + (size_t)s0 * 128 + lane * 4);
            const float4 k1 = *(const float4*)(g_k + (size_t)s1 * 128 + lane * 4);
            const float4 k2 = *(const float4*)(g_k + (size_t)s2 * 128 + lane * 4);
            const float4 k3 = *(const float4*)(g_k + (size_t)s3 * 128 + lane * 4);

            float p0 = lrelu(qv.x + k0.x) * a0 + lrelu(qv.y + k0.y) * a1 +
                       lrelu(qv.z + k0.z) * a2 + lrelu(qv.w + k0.w) * a3;
            float p1 = lrelu(qv.x + k1.x) * a0 + lrelu(qv.y + k1.y) * a1 +
                       lrelu(qv.z + k1.z) * a2 + lrelu(qv.w + k1.w) * a3;
            float p2 = lrelu(qv.x + k2.x) * a0 + lrelu(qv.y + k2.y) * a1 +
                       lrelu(qv.z + k2.z) * a2 + lrelu(qv.w + k2.w) * a3;
            float p3 = lrelu(qv.x + k3.x) * a0 + lrelu(qv.y + k3.y) * a1 +
                       lrelu(qv.z + k3.z) * a2 + lrelu(qv.w + k3.w) * a3;

            p0 += __shfl_xor_sync(0xffffffffu, p0, 1);
            p1 += __shfl_xor_sync(0xffffffffu, p1, 1);
            p2 += __shfl_xor_sync(0xffffffffu, p2, 1);
            p3 += __shfl_xor_sync(0xffffffffu, p3, 1);
            p0 += __shfl_xor_sync(0xffffffffu, p0, 2);
            p1 += __shfl_xor_sync(0xffffffffu, p1, 2);
            p2 += __shfl_xor_sync(0xffffffffu, p2, 2);
            p3 += __shfl_xor_sync(0xffffffffu, p3, 2);

            const float u0 = __expf(p0);
            const float u1 = __expf(p1);
            const float u2 = __expf(p2);
            const float u3 = __expf(p3);

            acc.x += u0 * k0.x + u1 * k1.x + u2 * k2.x + u3 * k3.x;
            acc.y += u0 * k0.y + u1 * k1.y + u2 * k2.y + u3 * k3.y;
            acc.z += u0 * k0.z + u1 * k1.z + u2 * k2.z + u3 * k3.z;
            acc.w += u0 * k0.w + u1 * k1.w + u2 * k2.w + u3 * k3.w;
            dsum += (u0 + u1) + (u2 + u3);
        }
        for (; j < cnt; j++) {
            const int s0 = __shfl_sync(0xffffffffu, src_l, j);
            const float4 k0 = *(const float4*)(g_k + (size_t)s0 * 128 + lane * 4);
            float p0 = lrelu(qv.x + k0.x) * a0 + lrelu(qv.y + k0.y) * a1 +
                       lrelu(qv.z + k0.z) * a2 + lrelu(qv.w + k0.w) * a3;
            p0 += __shfl_xor_sync(0xffffffffu, p0, 1);
            p0 += __shfl_xor_sync(0xffffffffu, p0, 2);
            const float u0 = __expf(p0);
            acc.x += u0 * k0.x;
            acc.y += u0 * k0.y;
            acc.z += u0 * k0.z;
            acc.w += u0 * k0.w;
            dsum += u0;
        }
    }

    const float inv = (dsum > 0.f) ? 1.f / dsum : 0.f;
    float4 o;
    o.x = fmaxf(acc.x * inv, 0.f);
    o.y = fmaxf(acc.y * inv, 0.f);
    o.z = fmaxf(acc.z * inv, 0.f);
    o.w = fmaxf(acc.w * inv, 0.f);
    *(float4*)(out + (size_t)node * 128 + lane * 4) = o;
}

// ---------------- launch ------------------------------------------------------
extern "C" void kernel_launch(void* const* d_in, const int* in_sizes, int n_in,
                              void* d_out, int out_size) {
    const float* x    = (const float*)d_in[0];
    const float* wq   = (const float*)d_in[1];
    const float* bq   = (const float*)d_in[2];
    const float* wk   = (const float*)d_in[3];
    const float* bk   = (const float*)d_in[4];
    const float* attn = (const float*)d_in[5];
    const int*   esrc = (const int*)d_in[6];
    const int*   etgt = (const int*)d_in[7];
    float* out = (float*)d_out;

    void* count_ptr = nullptr;
    cudaGetSymbolAddress(&count_ptr, g_count);

    // ---- fork: CSR build on side stream, GEMM on main stream (overlapped) ----
    cudaEventRecord(g_ev_fork, 0);
    cudaStreamWaitEvent(g_s2, g_ev_fork, 0);

    cudaMemsetAsync(count_ptr, 0, N_NODES * sizeof(int), g_s2);
    hist_kernel<<<(N_EDGES + 255) / 256, 256, 0, g_s2>>>(etgt);
    scan_kernel<<<1, SCAN_THREADS, 0, g_s2>>>();
    scatter_kernel<<<(N_EDGES + 255) / 256, 256, 0, g_s2>>>(esrc, etgt);
    cudaEventRecord(g_ev_join, g_s2);

    // main stream: persistent broadcast-w Q/K GEMM (~65.3KB smem, 3 CTAs/SM)
    static const size_t gemm_smem = (8192 + 8448 + 64) * sizeof(float);
    cudaFuncSetAttribute(qk_gemm_kernel, cudaFuncAttributeMaxDynamicSharedMemorySize,
                         (int)gemm_smem);
    dim3 gemm_grid(GEMM_GRID_X, 4);
    qk_gemm_kernel<<<gemm_grid, GEMM_BLOCK, gemm_smem>>>(x, wq, bq, wk, bk);

    // ---- join: gather needs both GEMM (program order) and CSR (event) -------
    cudaStreamWaitEvent(0, g_ev_join, 0);
    gather_kernel<<<(N_NODES * 32 + 255) / 256, 256>>>(attn, out);
}

// round 13
// speedup vs baseline: 1.5330x; 1.4785x over previous
#include <cuda_runtime.h>
#include <cuda_bf16.h>
#include <cstdint>

#define N_NODES 50000
#define N_EDGES 800000
#define D_IN 128
#define N_HEADS 8
#define PER_HEAD 16
#define LEAKY_ALPHA 0.2f

// ---------------- static device scratch (no allocations allowed) ------------
__device__ float g_q[(size_t)N_NODES * 128];         // 25.6 MB
__device__ float g_k[(size_t)N_NODES * 128];         // 25.6 MB
__device__ int   g_count[N_NODES];                   // in-degree histogram
__device__ int   g_offset[N_NODES + 1];              // CSR row offsets
__device__ int   g_cursor[N_NODES];                  // scatter cursors
__device__ int   g_src_sorted[N_EDGES];              // src node per CSR slot

__device__ __forceinline__ float lrelu(float v) {
    return v > 0.0f ? v : LEAKY_ALPHA * v;
}

__device__ __forceinline__ uint32_t f2tf32(float f) {
    uint32_t r;
    asm("cvt.rna.tf32.f32 %0, %1;" : "=r"(r) : "f"(f));
    return r;
}

__device__ __forceinline__ void mma_tf32(float c[4],
                                         uint32_t a0, uint32_t a1, uint32_t a2, uint32_t a3,
                                         uint32_t b0, uint32_t b1) {
    asm volatile(
        "mma.sync.aligned.m16n8k8.row.col.f32.tf32.tf32.f32 "
        "{%0,%1,%2,%3}, {%4,%5,%6,%7}, {%8,%9}, {%0,%1,%2,%3};"
        : "+f"(c[0]), "+f"(c[1]), "+f"(c[2]), "+f"(c[3])
        : "r"(a0), "r"(a1), "r"(a2), "r"(a3), "r"(b0), "r"(b1));
}

// ---------------- Kernel 1: Q/K GEMM on tensor cores (tf32 mma.sync) ---------
// Block = 256 threads (8 warps), 2 CTAs/SM. blockIdx.y selects Wq (0) or Wk (1)
// -- the whole 128x128 weight lives in smem as tf32, loaded ONCE per block
// (persistent node-tile loop). Per iter: stage 64 nodes x 128 dims to tf32 smem,
// then 8 warps compute a 64x128 output tile: warp = 16 rows x 64 cols =
// 8 x (m16n8k8) n-tiles x 16 k-steps. fp32 accumulate, bias in fp32 epilogue.
// Bank design: xs stride 132 words -> A-frag banks (4g+tid) unique;
//              ws stride 136 words -> B-frag banks (8*tid+g) unique.
#define GEMM_BLOCK 256
#define GEMM_TILE_N 64
#define WS_STRIDE 136
#define XS_STRIDE 132
#define N_NODE_TILES ((N_NODES + GEMM_TILE_N - 1) / GEMM_TILE_N)  // 782

__global__ void __launch_bounds__(GEMM_BLOCK, 2)
qk_gemm_tc_kernel(const float* __restrict__ x,
                  const float* __restrict__ wq, const float* __restrict__ bq,
                  const float* __restrict__ wk, const float* __restrict__ bk) {
    extern __shared__ uint32_t smem_u[];
    uint32_t* ws = smem_u;                        // [128][136] = 17408 words
    uint32_t* xs = smem_u + 128 * WS_STRIDE;      // [64][132]  = 8448 words
    float* bs = (float*)(xs + GEMM_TILE_N * XS_STRIDE);  // 128 floats

    const int t = threadIdx.x;
    const bool is_q = (blockIdx.y == 0);
    const float* wsrc = is_q ? wq : wk;
    const float* bsrc = is_q ? bq : bk;
    float* gout = is_q ? g_q : g_k;

    // stage full 128x128 weight as tf32 (once per block; coalesced)
    for (int i = t; i < 128 * 128; i += GEMM_BLOCK) {
        int k = i >> 7, c = i & 127;
        ws[k * WS_STRIDE + c] = f2tf32(wsrc[i]);
    }
    if (t < 128) bs[t] = bsrc[t];

    const int warp = t >> 5;
    const int lane = t & 31;
    const int g = lane >> 2;       // groupID 0..7
    const int tid4 = lane & 3;     // threadID_in_group 0..3
    const int mb = (warp & 3) * 16;   // warp row base within 64
    const int nb = (warp >> 2) * 64;  // warp col base within 128

    for (int tile = blockIdx.x; tile < N_NODE_TILES; tile += gridDim.x) {
        const int n0 = tile * GEMM_TILE_N;
        __syncthreads();   // previous compute done (and joins weight staging)
        // stage 64 nodes x 128 dims -> tf32 (float4 read, uint4 write)
        for (int i = t; i < GEMM_TILE_N * 32; i += GEMM_BLOCK) {
            int n = i >> 5, c4 = i & 31;
            int gn = n0 + n;
            float4 v = make_float4(0.f, 0.f, 0.f, 0.f);
            if (gn < N_NODES) v = *(const float4*)(x + (size_t)gn * 128 + c4 * 4);
            uint4 u;
            u.x = f2tf32(v.x); u.y = f2tf32(v.y);
            u.z = f2tf32(v.z); u.w = f2tf32(v.w);
            *(uint4*)(xs + n * XS_STRIDE + c4 * 4) = u;
        }
        __syncthreads();

        float acc[8][4];
#pragma unroll
        for (int nt = 0; nt < 8; nt++)
#pragma unroll
            for (int c = 0; c < 4; c++) acc[nt][c] = 0.f;

#pragma unroll 4
        for (int k0 = 0; k0 < 128; k0 += 8) {
            const uint32_t a0 = xs[(mb + g) * XS_STRIDE + k0 + tid4];
            const uint32_t a1 = xs[(mb + g + 8) * XS_STRIDE + k0 + tid4];
            const uint32_t a2 = xs[(mb + g) * XS_STRIDE + k0 + tid4 + 4];
            const uint32_t a3 = xs[(mb + g + 8) * XS_STRIDE + k0 + tid4 + 4];
#pragma unroll
            for (int nt = 0; nt < 8; nt++) {
                const uint32_t b0 = ws[(k0 + tid4) * WS_STRIDE + nb + nt * 8 + g];
                const uint32_t b1 = ws[(k0 + tid4 + 4) * WS_STRIDE + nb + nt * 8 + g];
                mma_tf32(acc[nt], a0, a1, a2, a3, b0, b1);
            }
        }

        // epilogue: add bias, write float2 per (row, n-tile)
        const int r0 = n0 + mb + g;
        const int r1 = r0 + 8;
#pragma unroll
        for (int nt = 0; nt < 8; nt++) {
            const int col = nb + nt * 8 + tid4 * 2;
            const float b0v = bs[col];
            const float b1v = bs[col + 1];
            if (r0 < N_NODES) {
                float2 v = make_float2(acc[nt][0] + b0v, acc[nt][1] + b1v);
                *(float2*)(gout + (size_t)r0 * 128 + col) = v;
            }
            if (r1 < N_NODES) {
                float2 v = make_float2(acc[nt][2] + b0v, acc[nt][3] + b1v);
                *(float2*)(gout + (size_t)r1 * 128 + col) = v;
            }
        }
    }
}

// ---------------- CSR build: histogram -> scan -> scatter --------------------
__global__ void hist_kernel(const int* __restrict__ etgt) {
    int i = blockIdx.x * blockDim.x + threadIdx.x;
    if (i < N_EDGES) atomicAdd(&g_count[etgt[i]], 1);
}

#define SCAN_THREADS 1024
__global__ void scan_kernel() {
    __shared__ int partial[SCAN_THREADS];
    const int t = threadIdx.x;
    const int CHUNK = (N_NODES + SCAN_THREADS - 1) / SCAN_THREADS;  // 49
    const int base = t * CHUNK;

    int s = 0;
    for (int i = 0; i < CHUNK; i++) {
        int idx = base + i;
        if (idx < N_NODES) s += g_count[idx];
    }
    partial[t] = s;
    __syncthreads();

    for (int off = 1; off < SCAN_THREADS; off <<= 1) {
        int u = (t >= off) ? partial[t - off] : 0;
        __syncthreads();
        partial[t] += u;
        __syncthreads();
    }

    int run = partial[t] - s;
    for (int i = 0; i < CHUNK; i++) {
        int idx = base + i;
        if (idx < N_NODES) {
            g_offset[idx] = run;
            g_cursor[idx] = run;
            run += g_count[idx];
        }
    }
    if (t == SCAN_THREADS - 1) g_offset[N_NODES] = partial[SCAN_THREADS - 1];
}

__global__ void scatter_kernel(const int* __restrict__ esrc,
                               const int* __restrict__ etgt) {
    int i = blockIdx.x * blockDim.x + threadIdx.x;
    if (i < N_EDGES) {
        int pos = atomicAdd(&g_cursor[etgt[i]], 1);
        g_src_sorted[pos] = esrc[i];
    }
}

// ---------------- Kernel 2: per-node gather (exact R9 known-good, MLP=4) -----
__global__ void __launch_bounds__(256)
gather_kernel(const float* __restrict__ attn, float* __restrict__ out) {
    __shared__ float a_s[128];
    if (threadIdx.x < 128) a_s[threadIdx.x] = attn[threadIdx.x];
    __syncthreads();

    const int node = (blockIdx.x * blockDim.x + threadIdx.x) >> 5;
    if (node >= N_NODES) return;
    const int lane = threadIdx.x & 31;
    const int part = lane & 3;
    const int h = lane >> 2;

    const float a0 = a_s[(part * 4 + 0) * 8 + h];
    const float a1 = a_s[(part * 4 + 1) * 8 + h];
    const float a2 = a_s[(part * 4 + 2) * 8 + h];
    const float a3 = a_s[(part * 4 + 3) * 8 + h];

    const float4 qv = *(const float4*)(g_q + (size_t)node * 128 + lane * 4);

    const int start = g_offset[node];
    const int end = g_offset[node + 1];

    float4 acc = make_float4(0.f, 0.f, 0.f, 0.f);
    float dsum = 0.f;

    for (int b = start; b < end; b += 32) {
        const int cnt = min(32, end - b);
        const int src_l = (lane < cnt) ? g_src_sorted[b + lane] : 0;

        int j = 0;
        for (; j + 4 <= cnt; j += 4) {
            const int s0 = __shfl_sync(0xffffffffu, src_l, j);
            const int s1 = __shfl_sync(0xffffffffu, src_l, j + 1);
            const int s2 = __shfl_sync(0xffffffffu, src_l, j + 2);
            const int s3 = __shfl_sync(0xffffffffu, src_l, j + 3);
            const float4 k0 = *(const float4*)(g_k + (size_t)s0 * 128 + lane * 4);
            const float4 k1 = *(const float4*)(g_k + (size_t)s1 * 128 + lane * 4);
            const float4 k2 = *(const float4*)(g_k + (size_t)s2 * 128 + lane * 4);
            const float4 k3 = *(const float4*)(g_k + (size_t)s3 * 128 + lane * 4);

            float p0 = lrelu(qv.x + k0.x) * a0 + lrelu(qv.y + k0.y) * a1 +
                       lrelu(qv.z + k0.z) * a2 + lrelu(qv.w + k0.w) * a3;
            float p1 = lrelu(qv.x + k1.x) * a0 + lrelu(qv.y + k1.y) * a1 +
                       lrelu(qv.z + k1.z) * a2 + lrelu(qv.w + k1.w) * a3;
            float p2 = lrelu(qv.x + k2.x) * a0 + lrelu(qv.y + k2.y) * a1 +
                       lrelu(qv.z + k2.z) * a2 + lrelu(qv.w + k2.w) * a3;
            float p3 = lrelu(qv.x + k3.x) * a0 + lrelu(qv.y + k3.y) * a1 +
                       lrelu(qv.z + k3.z) * a2 + lrelu(qv.w + k3.w) * a3;

            p0 += __shfl_xor_sync(0xffffffffu, p0, 1);
            p1 += __shfl_xor_sync(0xffffffffu, p1, 1);
            p2 += __shfl_xor_sync(0xffffffffu, p2, 1);
            p3 += __shfl_xor_sync(0xffffffffu, p3, 1);
            p0 += __shfl_xor_sync(0xffffffffu, p0, 2);
            p1 += __shfl_xor_sync(0xffffffffu, p1, 2);
            p2 += __shfl_xor_sync(0xffffffffu, p2, 2);
            p3 += __shfl_xor_sync(0xffffffffu, p3, 2);

            const float u0 = __expf(p0);
            const float u1 = __expf(p1);
            const float u2 = __expf(p2);
            const float u3 = __expf(p3);

            acc.x += u0 * k0.x + u1 * k1.x + u2 * k2.x + u3 * k3.x;
            acc.y += u0 * k0.y + u1 * k1.y + u2 * k2.y + u3 * k3.y;
            acc.z += u0 * k0.z + u1 * k1.z + u2 * k2.z + u3 * k3.z;
            acc.w += u0 * k0.w + u1 * k1.w + u2 * k2.w + u3 * k3.w;
            dsum += (u0 + u1) + (u2 + u3);
        }
        for (; j < cnt; j++) {
            const int s0 = __shfl_sync(0xffffffffu, src_l, j);
            const float4 k0 = *(const float4*)(g_k + (size_t)s0 * 128 + lane * 4);
            float p0 = lrelu(qv.x + k0.x) * a0 + lrelu(qv.y + k0.y) * a1 +
                       lrelu(qv.z + k0.z) * a2 + lrelu(qv.w + k0.w) * a3;
            p0 += __shfl_xor_sync(0xffffffffu, p0, 1);
            p0 += __shfl_xor_sync(0xffffffffu, p0, 2);
            const float u0 = __expf(p0);
            acc.x += u0 * k0.x;
            acc.y += u0 * k0.y;
            acc.z += u0 * k0.z;
            acc.w += u0 * k0.w;
            dsum += u0;
        }
    }

    const float inv = (dsum > 0.f) ? 1.f / dsum : 0.f;
    float4 o;
    o.x = fmaxf(acc.x * inv, 0.f);
    o.y = fmaxf(acc.y * inv, 0.f);
    o.z = fmaxf(acc.z * inv, 0.f);
    o.w = fmaxf(acc.w * inv, 0.f);
    *(float4*)(out + (size_t)node * 128 + lane * 4) = o;
}

// ---------------- launch (serial; stream fork proven harmful in R10/R11) -----
extern "C" void kernel_launch(void* const* d_in, const int* in_sizes, int n_in,
                              void* d_out, int out_size) {
    const float* x    = (const float*)d_in[0];
    const float* wq   = (const float*)d_in[1];
    const float* bq   = (const float*)d_in[2];
    const float* wk   = (const float*)d_in[3];
    const float* bk   = (const float*)d_in[4];
    const float* attn = (const float*)d_in[5];
    const int*   esrc = (const int*)d_in[6];
    const int*   etgt = (const int*)d_in[7];
    float* out = (float*)d_out;

    // zero the degree histogram (symbol address query, no alloc)
    void* count_ptr = nullptr;
    cudaGetSymbolAddress(&count_ptr, g_count);
    cudaMemsetAsync(count_ptr, 0, N_NODES * sizeof(int), 0);

    // CSR build
    hist_kernel<<<(N_EDGES + 255) / 256, 256>>>(etgt);
    scan_kernel<<<1, SCAN_THREADS>>>();
    scatter_kernel<<<(N_EDGES + 255) / 256, 256>>>(esrc, etgt);

    // tensor-core Q/K GEMM: ~101.5KB smem, 2 CTAs/SM, persistent node loop
    static const size_t gemm_smem =
        (128 * WS_STRIDE + GEMM_TILE_N * XS_STRIDE) * 4 + 128 * 4;
    cudaFuncSetAttribute(qk_gemm_tc_kernel,
                         cudaFuncAttributeMaxDynamicSharedMemorySize,
                         (int)gemm_smem);
    dim3 gemm_grid(148, 2);
    qk_gemm_tc_kernel<<<gemm_grid, GEMM_BLOCK, gemm_smem>>>(x, wq, bq, wk, bk);

    // per-node gather: one warp per node, 8 nodes per 256-thread block
    gather_kernel<<<(N_NODES * 32 + 255) / 256, 256>>>(attn, out);
}